// round 8
// baseline (speedup 1.0000x reference)
#include <cuda_runtime.h>

// Problem constants (from reference setup_inputs)
#define BD   8        // batch
#define NN   2048     // N = O*K
#define HH   128      // hidden
#define TT   10       // pred_len
#define MAXN 256      // neighbor cap (avg degree ~10)
#define TR   32       // tile rows for fused agg+gemm kernels

// ---------------- device scratch (no allocations allowed) ----------------
__device__ float g_pos[BD * NN * 3];
__device__ float g_vel[BD * NN * 3];
__device__ __align__(16) float g_ha[BD * NN * HH];     // h ping
__device__ __align__(16) float g_hb[BD * NN * HH];     // h pong
__device__ int   g_nbr[BD * NN * MAXN];
__device__ int   g_cnt[BD * NN];
__device__ float g_dinv[BD * NN];

// ---------------- init: pos=points, vel=0, write t=0 output ----------------
__global__ void k_init(const float* __restrict__ pts, float* __restrict__ out) {
    int id = blockIdx.x * blockDim.x + threadIdx.x;   // over B*N*3
    if (id < BD * NN * 3) {
        float v = pts[id];
        g_pos[id] = v;
        g_vel[id] = 0.f;
        int c = id % 3;
        int n = (id / 3) % NN;
        int b = id / (3 * NN);
        out[((size_t)(b * (TT + 1)) * NN + n) * 3 + c] = v;
    }
}

// ---------------- adjacency + fused layer0 h --------------------------------
// grid (NN/64, BD), 256 threads.
__global__ __launch_bounds__(256) void k_adj(const float* __restrict__ padding,
                                             const float* __restrict__ W0) {
    __shared__ float px[NN], py[NN], pz[NN], pd[NN];
    __shared__ float W0s[6 * HH];
    __shared__ float sv[64][3];
    __shared__ float sdinv[64];
    int b = blockIdx.y, bN = b * NN;
    int i0 = blockIdx.x * 64;
    int tid = threadIdx.x;
    const float* pos = g_pos + (size_t)bN * 3;
    for (int j = tid; j < NN; j += 256) {
        px[j] = pos[j * 3 + 0];
        py[j] = pos[j * 3 + 1];
        pz[j] = pos[j * 3 + 2];
        pd[j] = padding[bN + j];
    }
    for (int k = tid; k < 6 * HH; k += 256) W0s[k] = W0[k];
    if (tid < 192) sv[tid / 3][tid % 3] = g_vel[(bN + i0 + tid / 3) * 3 + tid % 3];
    __syncthreads();

    int warp = tid >> 5, lane = tid & 31;
    const float R2 = 0.01f;   // float32(0.1*0.1), fp32 compare like the ref
    for (int r = 0; r < 8; r++) {
        int rr = r * 8 + warp;            // row-in-block 0..63
        int i = i0 + rr;
        float xi = px[i], yi = py[i], zi = pz[i];
        bool oki = pd[i] > 0.f;
        int base = (bN + i) * MAXN;
        int cnt = 0;
        #pragma unroll 4
        for (int t = 0; t < NN / 32; t++) {
            int j = t * 32 + lane;
            // separate mul/add rounding — matches XLA's sub/mul/reduce-add
            float dx = __fadd_rn(px[j], -xi);
            float dy = __fadd_rn(py[j], -yi);
            float dz = __fadd_rn(pz[j], -zi);
            float d2 = __fadd_rn(__fadd_rn(__fmul_rn(dx, dx), __fmul_rn(dy, dy)),
                                 __fmul_rn(dz, dz));
            // a_hat = adj + I: diagonal always 1; self at its sorted position
            bool hit = (j == i) || (oki && (pd[j] > 0.f) && (d2 < R2));
            unsigned m = __ballot_sync(0xffffffffu, hit);
            if (hit) {
                int off = cnt + __popc(m & ((1u << lane) - 1u));
                if (off < MAXN) g_nbr[base + off] = j;
            }
            cnt += __popc(m);
        }
        if (cnt > MAXN) cnt = MAXN;
        if (lane == 0) {
            // XLA lowers rsqrt as 1/sqrt (correctly rounded), NOT MUFU.RSQ.
            float di = 1.0f / sqrtf((float)cnt);
            g_cnt[bN + i]  = cnt;
            g_dinv[bN + i] = di;
            sdinv[rr] = di;
        }
    }
    __syncthreads();

    // layer0 h for own rows (ascending-k FMA, pos then vel)
    for (int o = tid; o < 64 * HH; o += 256) {
        int r = o >> 7, col = o & 127;
        float acc = 0.f;
        acc = fmaf(px[i0 + r], W0s[0 * HH + col], acc);
        acc = fmaf(py[i0 + r], W0s[1 * HH + col], acc);
        acc = fmaf(pz[i0 + r], W0s[2 * HH + col], acc);
        acc = fmaf(sv[r][0],   W0s[3 * HH + col], acc);
        acc = fmaf(sv[r][1],   W0s[4 * HH + col], acc);
        acc = fmaf(sv[r][2],   W0s[5 * HH + col], acc);
        g_ha[(size_t)(bN + i0 + r) * HH + col] = __fmul_rn(acc, sdinv[r]);
    }
}

// ---------------- fused aggregate + dense GEMM (32-row tiles) ---------------
// Phase A: x_i = relu((sum_{j in nbr_i} h_j)*dinv_i + bias)  -> smem xs
// Phase B: h'_i = (x_i @ W) * dinv_i  (W streamed via L1)     -> other h buf
// src==0: g_ha -> g_hb ; src==1: g_hb -> g_ha.
// grid (BD*NN/TR), 256 threads, static smem (~17.5KB) for high occupancy.
__global__ __launch_bounds__(256) void k_aggemm(int src,
                                                const float* __restrict__ bias,
                                                const float* __restrict__ W) {
    __shared__ __align__(16) float xs[TR * 132];  // pitch 132, float4-aligned
    __shared__ float dj[TR];
    __shared__ __align__(16) float bs[HH];

    const float* hin  = src ? g_hb : g_ha;
    float*       hout = src ? g_ha : g_hb;

    int row0 = blockIdx.x * TR;
    int tid = threadIdx.x;
    int bN = (row0 / NN) * NN;       // neighbors are batch-local ids

    if (tid < HH) bs[tid] = bias[tid];
    if (tid < TR) dj[tid] = g_dinv[row0 + tid];
    __syncthreads();

    // Phase A: one warp per row (4 rows/warp), float4 gather, ascending j.
    // Per-feature accumulation order identical to scalar version.
    int warp = tid >> 5, lane = tid & 31;
    for (int r = warp; r < TR; r += 8) {
        int i = row0 + r;
        int cnt = g_cnt[i];
        const int* nb = g_nbr + (size_t)i * MAXN;
        float4 a = make_float4(0.f, 0.f, 0.f, 0.f);
        for (int t = 0; t < cnt; t++) {
            const float4* hr = (const float4*)(hin + (size_t)(bN + nb[t]) * HH);
            float4 v = __ldg(hr + lane);
            a.x = __fadd_rn(a.x, v.x);
            a.y = __fadd_rn(a.y, v.y);
            a.z = __fadd_rn(a.z, v.z);
            a.w = __fadd_rn(a.w, v.w);
        }
        float di = dj[r];
        float4 bb = ((const float4*)bs)[lane];
        float4 o;
        o.x = fmaxf(__fadd_rn(__fmul_rn(a.x, di), bb.x), 0.f);
        o.y = fmaxf(__fadd_rn(__fmul_rn(a.y, di), bb.y), 0.f);
        o.z = fmaxf(__fadd_rn(__fmul_rn(a.z, di), bb.z), 0.f);
        o.w = fmaxf(__fadd_rn(__fmul_rn(a.w, di), bb.w), 0.f);
        *(float4*)&xs[r * 132 + lane * 4] = o;
    }
    __syncthreads();

    // Phase B: xs(32x128) @ W(128x128), W via __ldg (L1-resident, 64KB).
    // Ascending-k single-accumulator FMA — bit-identical to smem version.
    int tc = tid & 15, tr2 = tid >> 4;     // 8 cols x 2 rows per thread
    const float* y0 = xs + (2 * tr2) * 132;
    const float* y1 = y0 + 132;
    float acc[2][8];
    #pragma unroll
    for (int m = 0; m < 2; m++)
        #pragma unroll
        for (int n = 0; n < 8; n++) acc[m][n] = 0.f;

    const float4* Wv = (const float4*)W;   // W[k*128 + c] -> Wv[k*32 + c/4]
    #pragma unroll 4
    for (int k = 0; k < HH; k++) {
        float ya = y0[k], yb = y1[k];
        float4 w0 = __ldg(Wv + k * 32 + 2 * tc);
        float4 w1 = __ldg(Wv + k * 32 + 2 * tc + 1);
        float wv[8] = {w0.x, w0.y, w0.z, w0.w, w1.x, w1.y, w1.z, w1.w};
        #pragma unroll
        for (int n = 0; n < 8; n++) acc[0][n] = fmaf(ya, wv[n], acc[0][n]);
        #pragma unroll
        for (int n = 0; n < 8; n++) acc[1][n] = fmaf(yb, wv[n], acc[1][n]);
    }

    #pragma unroll
    for (int m = 0; m < 2; m++) {
        int r = 2 * tr2 + m;
        float d = dj[r];
        float o[8];
        #pragma unroll
        for (int n = 0; n < 8; n++) o[n] = __fmul_rn(acc[m][n], d);
        float4* dst = (float4*)&hout[(size_t)(row0 + r) * HH + 8 * tc];
        dst[0] = make_float4(o[0], o[1], o[2], o[3]);
        dst[1] = make_float4(o[4], o[5], o[6], o[7]);
    }
}

// ---------------- fused aggregate + fc head + state update ------------------
// Reads g_ha (layer2 gemm output lands there). 32-row tiles, grid ROWS/TR.
__global__ __launch_bounds__(256) void k_aggfc(const float* __restrict__ bias2,
                                               const float* __restrict__ Wfc,
                                               const float* __restrict__ bfc,
                                               const float* __restrict__ padding,
                                               float* __restrict__ out, int t) {
    __shared__ __align__(16) float xs[TR * 132];
    __shared__ float Wf[HH * 6];
    __shared__ float bf[6];
    __shared__ __align__(16) float bs[HH];
    int row0 = blockIdx.x * TR;
    int tid = threadIdx.x;
    int bN = (row0 / NN) * NN;

    for (int k = tid; k < HH * 6; k += 256) Wf[k] = Wfc[k];
    if (tid < 6) bf[tid] = bfc[tid];
    if (tid < HH) bs[tid] = bias2[tid];
    __syncthreads();

    int warp = tid >> 5, lane = tid & 31;
    for (int r = warp; r < TR; r += 8) {
        int i = row0 + r;
        int cnt = g_cnt[i];
        const int* nb = g_nbr + (size_t)i * MAXN;
        float4 a = make_float4(0.f, 0.f, 0.f, 0.f);
        for (int tt = 0; tt < cnt; tt++) {
            const float4* hr = (const float4*)(g_ha + (size_t)(bN + nb[tt]) * HH);
            float4 v = __ldg(hr + lane);
            a.x = __fadd_rn(a.x, v.x);
            a.y = __fadd_rn(a.y, v.y);
            a.z = __fadd_rn(a.z, v.z);
            a.w = __fadd_rn(a.w, v.w);
        }
        float di = g_dinv[i];
        float4 bb = ((const float4*)bs)[lane];
        float4 o;
        o.x = fmaxf(__fadd_rn(__fmul_rn(a.x, di), bb.x), 0.f);
        o.y = fmaxf(__fadd_rn(__fmul_rn(a.y, di), bb.y), 0.f);
        o.z = fmaxf(__fadd_rn(__fmul_rn(a.z, di), bb.z), 0.f);
        o.w = fmaxf(__fadd_rn(__fmul_rn(a.w, di), bb.w), 0.f);
        *(float4*)&xs[r * 132 + lane * 4] = o;
    }
    __syncthreads();

    for (int w = tid; w < TR * 6; w += 256) {
        int r = w / 6, c = w % 6;
        int g = row0 + r;
        const float* xr = xs + r * 132;
        float acc = 0.f;
        #pragma unroll 8
        for (int k = 0; k < HH; k++) acc = fmaf(xr[k], Wf[k * 6 + c], acc);
        float res = __fadd_rn(acc, bf[c]);
        res = __fmul_rn(res, padding[g]);
        if (c < 3) {
            float p = __fadd_rn(g_pos[g * 3 + c], res);
            g_pos[g * 3 + c] = p;
            int b = g / NN, n = g % NN;
            out[((size_t)(b * (TT + 1) + t + 1) * NN + n) * 3 + c] = p;
        } else {
            int a = g * 3 + (c - 3);
            g_vel[a] = __fadd_rn(g_vel[a], res);
        }
    }
}

// ---------------- launch ----------------
extern "C" void kernel_launch(void* const* d_in, const int* in_sizes, int n_in,
                              void* d_out, int out_size) {
    const float* points  = (const float*)d_in[0];
    const float* padding = (const float*)d_in[5];
    const float* W0  = (const float*)d_in[6];
    const float* b0  = (const float*)d_in[7];
    const float* W1  = (const float*)d_in[8];
    const float* b1  = (const float*)d_in[9];
    const float* W2  = (const float*)d_in[10];
    const float* b2  = (const float*)d_in[11];
    const float* Wfc = (const float*)d_in[12];
    const float* bfc = (const float*)d_in[13];
    float* out = (float*)d_out;

    const int ROWS = BD * NN;

    k_init<<<(BD * NN * 3 + 255) / 256, 256>>>(points, out);

    for (int t = 0; t < TT; t++) {
        k_adj<<<dim3(NN / 64, BD), 256>>>(padding, W0);      // -> g_ha (h0)
        k_aggemm<<<ROWS / TR, 256>>>(0, b0, W1);             // ha -> x -> hb
        k_aggemm<<<ROWS / TR, 256>>>(1, b1, W2);             // hb -> x -> ha
        k_aggfc <<<ROWS / TR, 256>>>(b2, Wfc, bfc, padding, out, t);
    }
}

// round 10
// speedup vs baseline: 1.0860x; 1.0860x over previous
#include <cuda_runtime.h>

// Problem constants (from reference setup_inputs)
#define BD   8        // batch
#define NN   2048     // N = O*K
#define HH   128      // hidden
#define TT   10       // pred_len
#define MAXN 256      // neighbor cap (avg degree ~10)

// ---------------- device scratch (no allocations allowed) ----------------
__device__ float g_pos[BD * NN * 3];
__device__ float g_vel[BD * NN * 3];
__device__ __align__(16) float g_ha[BD * NN * HH];     // h ping
__device__ __align__(16) float g_hb[BD * NN * HH];     // h pong
__device__ int   g_nbr[BD * NN * MAXN];
__device__ int   g_cnt[BD * NN];
__device__ float g_dinv[BD * NN];

// ---------------- init: pos=points, vel=0, write t=0 output ----------------
__global__ void k_init(const float* __restrict__ pts, float* __restrict__ out) {
    int id = blockIdx.x * blockDim.x + threadIdx.x;   // over B*N*3
    if (id < BD * NN * 3) {
        float v = pts[id];
        g_pos[id] = v;
        g_vel[id] = 0.f;
        int c = id % 3;
        int n = (id / 3) % NN;
        int b = id / (3 * NN);
        out[((size_t)(b * (TT + 1)) * NN + n) * 3 + c] = v;
    }
}

// ---------------- adjacency + fused layer0 h --------------------------------
// grid (NN/64, BD), 256 threads.
__global__ __launch_bounds__(256) void k_adj(const float* __restrict__ padding,
                                             const float* __restrict__ W0) {
    __shared__ float px[NN], py[NN], pz[NN], pd[NN];
    __shared__ float W0s[6 * HH];
    __shared__ float sv[64][3];
    __shared__ float sdinv[64];
    int b = blockIdx.y, bN = b * NN;
    int i0 = blockIdx.x * 64;
    int tid = threadIdx.x;
    const float* pos = g_pos + (size_t)bN * 3;
    for (int j = tid; j < NN; j += 256) {
        px[j] = pos[j * 3 + 0];
        py[j] = pos[j * 3 + 1];
        pz[j] = pos[j * 3 + 2];
        pd[j] = padding[bN + j];
    }
    for (int k = tid; k < 6 * HH; k += 256) W0s[k] = W0[k];
    if (tid < 192) sv[tid / 3][tid % 3] = g_vel[(bN + i0 + tid / 3) * 3 + tid % 3];
    __syncthreads();

    int warp = tid >> 5, lane = tid & 31;
    const float R2 = 0.01f;   // float32(0.1*0.1), fp32 compare like the ref
    for (int r = 0; r < 8; r++) {
        int rr = r * 8 + warp;            // row-in-block 0..63
        int i = i0 + rr;
        float xi = px[i], yi = py[i], zi = pz[i];
        bool oki = pd[i] > 0.f;
        int base = (bN + i) * MAXN;
        int cnt = 0;
        #pragma unroll 4
        for (int t = 0; t < NN / 32; t++) {
            int j = t * 32 + lane;
            // separate mul/add rounding — matches XLA's sub/mul/reduce-add
            float dx = __fadd_rn(px[j], -xi);
            float dy = __fadd_rn(py[j], -yi);
            float dz = __fadd_rn(pz[j], -zi);
            float d2 = __fadd_rn(__fadd_rn(__fmul_rn(dx, dx), __fmul_rn(dy, dy)),
                                 __fmul_rn(dz, dz));
            // a_hat = adj + I: diagonal always 1; self at its sorted position
            bool hit = (j == i) || (oki && (pd[j] > 0.f) && (d2 < R2));
            unsigned m = __ballot_sync(0xffffffffu, hit);
            if (hit) {
                int off = cnt + __popc(m & ((1u << lane) - 1u));
                if (off < MAXN) g_nbr[base + off] = j;
            }
            cnt += __popc(m);
        }
        if (cnt > MAXN) cnt = MAXN;
        if (lane == 0) {
            // XLA lowers rsqrt as 1/sqrt (correctly rounded), NOT MUFU.RSQ.
            float di = 1.0f / sqrtf((float)cnt);
            g_cnt[bN + i]  = cnt;
            g_dinv[bN + i] = di;
            sdinv[rr] = di;
        }
    }
    __syncthreads();

    // layer0 h for own rows (ascending-k FMA, pos then vel)
    for (int o = tid; o < 64 * HH; o += 256) {
        int r = o >> 7, col = o & 127;
        float acc = 0.f;
        acc = fmaf(px[i0 + r], W0s[0 * HH + col], acc);
        acc = fmaf(py[i0 + r], W0s[1 * HH + col], acc);
        acc = fmaf(pz[i0 + r], W0s[2 * HH + col], acc);
        acc = fmaf(sv[r][0],   W0s[3 * HH + col], acc);
        acc = fmaf(sv[r][1],   W0s[4 * HH + col], acc);
        acc = fmaf(sv[r][2],   W0s[5 * HH + col], acc);
        g_ha[(size_t)(bN + i0 + r) * HH + col] = __fmul_rn(acc, sdinv[r]);
    }
}

// MLP-4 gather: 4 independent LDG.128 in flight, then ordered adds
// (strictly ascending t — bit-identical to the serial loop).
__device__ __forceinline__ float4 gather_row(const float* __restrict__ hin,
                                             const int* __restrict__ nb,
                                             int cnt, int bN, int lane) {
    float4 a = make_float4(0.f, 0.f, 0.f, 0.f);
    int t = 0;
    for (; t + 4 <= cnt; t += 4) {
        int j0 = nb[t], j1 = nb[t + 1], j2 = nb[t + 2], j3 = nb[t + 3];
        float4 v0 = __ldg((const float4*)(hin + (size_t)(bN + j0) * HH) + lane);
        float4 v1 = __ldg((const float4*)(hin + (size_t)(bN + j1) * HH) + lane);
        float4 v2 = __ldg((const float4*)(hin + (size_t)(bN + j2) * HH) + lane);
        float4 v3 = __ldg((const float4*)(hin + (size_t)(bN + j3) * HH) + lane);
        a.x = __fadd_rn(a.x, v0.x); a.y = __fadd_rn(a.y, v0.y);
        a.z = __fadd_rn(a.z, v0.z); a.w = __fadd_rn(a.w, v0.w);
        a.x = __fadd_rn(a.x, v1.x); a.y = __fadd_rn(a.y, v1.y);
        a.z = __fadd_rn(a.z, v1.z); a.w = __fadd_rn(a.w, v1.w);
        a.x = __fadd_rn(a.x, v2.x); a.y = __fadd_rn(a.y, v2.y);
        a.z = __fadd_rn(a.z, v2.z); a.w = __fadd_rn(a.w, v2.w);
        a.x = __fadd_rn(a.x, v3.x); a.y = __fadd_rn(a.y, v3.y);
        a.z = __fadd_rn(a.z, v3.z); a.w = __fadd_rn(a.w, v3.w);
    }
    for (; t < cnt; t++) {
        float4 v = __ldg((const float4*)(hin + (size_t)(bN + nb[t]) * HH) + lane);
        a.x = __fadd_rn(a.x, v.x); a.y = __fadd_rn(a.y, v.y);
        a.z = __fadd_rn(a.z, v.z); a.w = __fadd_rn(a.w, v.w);
    }
    return a;
}

// ---------------- fused aggregate + dense GEMM (64-row tiles) ---------------
// Phase A: x_i = relu((sum_{j in nbr_i} h_j)*dinv_i + bias)  -> smem xs
// Phase B: h'_i = (x_i @ W) * dinv_i  (W in smem)             -> other h buf
// src==0: g_ha -> g_hb ; src==1: g_hb -> g_ha.
// grid (BD*NN/64), 256 threads, dynamic smem (~98KB, 2 CTAs/SM).
__global__ __launch_bounds__(256) void k_aggemm(int src,
                                                const float* __restrict__ bias,
                                                const float* __restrict__ W) {
    extern __shared__ __align__(16) float sm[];
    float* Ws = sm;                 // 128*128
    float* xs = sm + HH * HH;       // 64*132 (float4-aligned pitch)
    float* dj = xs + 64 * 132;      // 64
    float* bs = dj + 64;            // 128

    const float* hin  = src ? g_hb : g_ha;
    float*       hout = src ? g_ha : g_hb;

    int row0 = blockIdx.x * 64;
    int tid = threadIdx.x;
    int bN = (row0 / NN) * NN;       // neighbors are batch-local ids

    for (int k = tid; k < HH * HH; k += 256) Ws[k] = W[k];
    if (tid < HH) bs[tid] = bias[tid];
    if (tid < 64) dj[tid] = g_dinv[row0 + tid];
    __syncthreads();

    // Phase A: one warp per row (8 rows/warp), MLP-4 float4 gather.
    int warp = tid >> 5, lane = tid & 31;
    for (int r = warp; r < 64; r += 8) {
        int i = row0 + r;
        float4 a = gather_row(hin, g_nbr + (size_t)i * MAXN, g_cnt[i], bN, lane);
        float di = dj[r];
        float4 bb = ((const float4*)bs)[lane];
        float4 o;
        o.x = fmaxf(__fadd_rn(__fmul_rn(a.x, di), bb.x), 0.f);
        o.y = fmaxf(__fadd_rn(__fmul_rn(a.y, di), bb.y), 0.f);
        o.z = fmaxf(__fadd_rn(__fmul_rn(a.z, di), bb.z), 0.f);
        o.w = fmaxf(__fadd_rn(__fmul_rn(a.w, di), bb.w), 0.f);
        *(float4*)&xs[r * 132 + lane * 4] = o;
    }
    __syncthreads();

    // Phase B: xs(64x128) @ Ws(128x128), ascending-k single-accumulator FMA.
    int tc = tid & 15, tr = tid >> 4;      // 16 col-groups x 16 row-groups
    float acc[4][8];
    #pragma unroll
    for (int m = 0; m < 4; m++)
        #pragma unroll
        for (int n = 0; n < 8; n++) acc[m][n] = 0.f;

    const float* yb = xs + (4 * tr) * 132;
    #pragma unroll 4
    for (int k = 0; k < HH; k++) {
        float yv[4] = {yb[k], yb[132 + k], yb[264 + k], yb[396 + k]};
        float4 w0 = *(const float4*)&Ws[k * HH + 8 * tc];
        float4 w1 = *(const float4*)&Ws[k * HH + 8 * tc + 4];
        float wv[8] = {w0.x, w0.y, w0.z, w0.w, w1.x, w1.y, w1.z, w1.w};
        #pragma unroll
        for (int m = 0; m < 4; m++)
            #pragma unroll
            for (int n = 0; n < 8; n++) acc[m][n] = fmaf(yv[m], wv[n], acc[m][n]);
    }

    #pragma unroll
    for (int m = 0; m < 4; m++) {
        int r = 4 * tr + m;
        float d = dj[r];
        float o[8];
        #pragma unroll
        for (int n = 0; n < 8; n++) o[n] = __fmul_rn(acc[m][n], d);
        float4* dst = (float4*)&hout[(size_t)(row0 + r) * HH + 8 * tc];
        dst[0] = make_float4(o[0], o[1], o[2], o[3]);
        dst[1] = make_float4(o[4], o[5], o[6], o[7]);
    }
}

// ---------------- fused aggregate + fc head + state update ------------------
// Reads g_ha (layer2 gemm output lands there). 64-row tiles.
__global__ __launch_bounds__(256) void k_aggfc(const float* __restrict__ bias2,
                                               const float* __restrict__ Wfc,
                                               const float* __restrict__ bfc,
                                               const float* __restrict__ padding,
                                               float* __restrict__ out, int t) {
    __shared__ __align__(16) float xs[64 * 132];
    __shared__ float Wf[HH * 6];
    __shared__ float bf[6];
    __shared__ __align__(16) float bs[HH];
    int row0 = blockIdx.x * 64;
    int tid = threadIdx.x;
    int bN = (row0 / NN) * NN;

    for (int k = tid; k < HH * 6; k += 256) Wf[k] = Wfc[k];
    if (tid < 6) bf[tid] = bfc[tid];
    if (tid < HH) bs[tid] = bias2[tid];
    __syncthreads();

    int warp = tid >> 5, lane = tid & 31;
    for (int r = warp; r < 64; r += 8) {
        int i = row0 + r;
        float4 a = gather_row(g_ha, g_nbr + (size_t)i * MAXN, g_cnt[i], bN, lane);
        float di = g_dinv[i];
        float4 bb = ((const float4*)bs)[lane];
        float4 o;
        o.x = fmaxf(__fadd_rn(__fmul_rn(a.x, di), bb.x), 0.f);
        o.y = fmaxf(__fadd_rn(__fmul_rn(a.y, di), bb.y), 0.f);
        o.z = fmaxf(__fadd_rn(__fmul_rn(a.z, di), bb.z), 0.f);
        o.w = fmaxf(__fadd_rn(__fmul_rn(a.w, di), bb.w), 0.f);
        *(float4*)&xs[r * 132 + lane * 4] = o;
    }
    __syncthreads();

    for (int w = tid; w < 64 * 6; w += 256) {
        int r = w / 6, c = w % 6;
        int g = row0 + r;
        const float* xr = xs + r * 132;
        float acc = 0.f;
        #pragma unroll 8
        for (int k = 0; k < HH; k++) acc = fmaf(xr[k], Wf[k * 6 + c], acc);
        float res = __fadd_rn(acc, bf[c]);
        res = __fmul_rn(res, padding[g]);
        if (c < 3) {
            float p = __fadd_rn(g_pos[g * 3 + c], res);
            g_pos[g * 3 + c] = p;
            int b = g / NN, n = g % NN;
            out[((size_t)(b * (TT + 1) + t + 1) * NN + n) * 3 + c] = p;
        } else {
            int a = g * 3 + (c - 3);
            g_vel[a] = __fadd_rn(g_vel[a], res);
        }
    }
}

// ---------------- launch ----------------
extern "C" void kernel_launch(void* const* d_in, const int* in_sizes, int n_in,
                              void* d_out, int out_size) {
    const float* points  = (const float*)d_in[0];
    const float* padding = (const float*)d_in[5];
    const float* W0  = (const float*)d_in[6];
    const float* b0  = (const float*)d_in[7];
    const float* W1  = (const float*)d_in[8];
    const float* b1  = (const float*)d_in[9];
    const float* W2  = (const float*)d_in[10];
    const float* b2  = (const float*)d_in[11];
    const float* Wfc = (const float*)d_in[12];
    const float* bfc = (const float*)d_in[13];
    float* out = (float*)d_out;

    const int smem_ag = (HH * HH + 64 * 132 + 64 + HH) * (int)sizeof(float);
    cudaFuncSetAttribute(k_aggemm, cudaFuncAttributeMaxDynamicSharedMemorySize,
                         smem_ag);

    const int ROWS = BD * NN;

    k_init<<<(BD * NN * 3 + 255) / 256, 256>>>(points, out);

    for (int t = 0; t < TT; t++) {
        k_adj<<<dim3(NN / 64, BD), 256>>>(padding, W0);      // -> g_ha (h0)
        k_aggemm<<<ROWS / 64, 256, smem_ag>>>(0, b0, W1);    // ha -> x -> hb
        k_aggemm<<<ROWS / 64, 256, smem_ag>>>(1, b1, W2);    // hb -> x -> ha
        k_aggfc <<<ROWS / 64, 256>>>(b2, Wfc, bfc, padding, out, t);
    }
}

// round 11
// speedup vs baseline: 1.2773x; 1.1761x over previous
#include <cuda_runtime.h>

// Problem constants (from reference setup_inputs)
#define BD   8        // batch
#define NN   2048     // N = O*K
#define HH   128      // hidden
#define TT   10       // pred_len
#define MAXN 256      // neighbor cap (avg degree ~10)

// ---------------- device scratch (no allocations allowed) ----------------
__device__ float g_pos[BD * NN * 3];
__device__ float g_vel[BD * NN * 3];
__device__ __align__(16) float g_ha[BD * NN * HH];     // h ping
__device__ __align__(16) float g_hb[BD * NN * HH];     // h pong
__device__ int   g_nbr[BD * NN * MAXN];
__device__ int   g_cnt[BD * NN];
__device__ float g_dinv[BD * NN];

// ---------------- init: pos=points, vel=0, write t=0 output ----------------
__global__ void k_init(const float* __restrict__ pts, float* __restrict__ out) {
    int id = blockIdx.x * blockDim.x + threadIdx.x;   // over B*N*3
    if (id < BD * NN * 3) {
        float v = pts[id];
        g_pos[id] = v;
        g_vel[id] = 0.f;
        int c = id % 3;
        int n = (id / 3) % NN;
        int b = id / (3 * NN);
        out[((size_t)(b * (TT + 1)) * NN + n) * 3 + c] = v;
    }
}

// ---------------- adjacency + fused layer0 h --------------------------------
// grid (NN/64, BD), 256 threads.
__global__ __launch_bounds__(256) void k_adj(const float* __restrict__ padding,
                                             const float* __restrict__ W0) {
    __shared__ float px[NN], py[NN], pz[NN], pd[NN];
    __shared__ float W0s[6 * HH];
    __shared__ float sv[64][3];
    __shared__ float sdinv[64];
    int b = blockIdx.y, bN = b * NN;
    int i0 = blockIdx.x * 64;
    int tid = threadIdx.x;
    const float* pos = g_pos + (size_t)bN * 3;
    for (int j = tid; j < NN; j += 256) {
        px[j] = pos[j * 3 + 0];
        py[j] = pos[j * 3 + 1];
        pz[j] = pos[j * 3 + 2];
        pd[j] = padding[bN + j];
    }
    for (int k = tid; k < 6 * HH; k += 256) W0s[k] = W0[k];
    if (tid < 192) sv[tid / 3][tid % 3] = g_vel[(bN + i0 + tid / 3) * 3 + tid % 3];
    __syncthreads();

    int warp = tid >> 5, lane = tid & 31;
    const float R2 = 0.01f;   // float32(0.1*0.1), fp32 compare like the ref
    for (int r = 0; r < 8; r++) {
        int rr = r * 8 + warp;            // row-in-block 0..63
        int i = i0 + rr;
        float xi = px[i], yi = py[i], zi = pz[i];
        bool oki = pd[i] > 0.f;
        int base = (bN + i) * MAXN;
        int cnt = 0;
        #pragma unroll 4
        for (int t = 0; t < NN / 32; t++) {
            int j = t * 32 + lane;
            // separate mul/add rounding — matches XLA's sub/mul/reduce-add
            float dx = __fadd_rn(px[j], -xi);
            float dy = __fadd_rn(py[j], -yi);
            float dz = __fadd_rn(pz[j], -zi);
            float d2 = __fadd_rn(__fadd_rn(__fmul_rn(dx, dx), __fmul_rn(dy, dy)),
                                 __fmul_rn(dz, dz));
            // a_hat = adj + I: diagonal always 1; self at its sorted position
            bool hit = (j == i) || (oki && (pd[j] > 0.f) && (d2 < R2));
            unsigned m = __ballot_sync(0xffffffffu, hit);
            if (hit) {
                int off = cnt + __popc(m & ((1u << lane) - 1u));
                if (off < MAXN) g_nbr[base + off] = j;
            }
            cnt += __popc(m);
        }
        if (cnt > MAXN) cnt = MAXN;
        if (lane == 0) {
            // XLA lowers rsqrt as 1/sqrt (correctly rounded), NOT MUFU.RSQ.
            float di = 1.0f / sqrtf((float)cnt);
            g_cnt[bN + i]  = cnt;
            g_dinv[bN + i] = di;
            sdinv[rr] = di;
        }
    }
    __syncthreads();

    // layer0 h for own rows (ascending-k FMA, pos then vel)
    for (int o = tid; o < 64 * HH; o += 256) {
        int r = o >> 7, col = o & 127;
        float acc = 0.f;
        acc = fmaf(px[i0 + r], W0s[0 * HH + col], acc);
        acc = fmaf(py[i0 + r], W0s[1 * HH + col], acc);
        acc = fmaf(pz[i0 + r], W0s[2 * HH + col], acc);
        acc = fmaf(sv[r][0],   W0s[3 * HH + col], acc);
        acc = fmaf(sv[r][1],   W0s[4 * HH + col], acc);
        acc = fmaf(sv[r][2],   W0s[5 * HH + col], acc);
        g_ha[(size_t)(bN + i0 + r) * HH + col] = __fmul_rn(acc, sdinv[r]);
    }
}

// MLP-4 gather: 4 independent LDG.128 in flight, then ordered adds
// (strictly ascending t — bit-identical to the serial loop).
__device__ __forceinline__ float4 gather_row(const float* __restrict__ hin,
                                             const int* __restrict__ nb,
                                             int cnt, int bN, int lane) {
    float4 a = make_float4(0.f, 0.f, 0.f, 0.f);
    int t = 0;
    for (; t + 4 <= cnt; t += 4) {
        int j0 = nb[t], j1 = nb[t + 1], j2 = nb[t + 2], j3 = nb[t + 3];
        float4 v0 = __ldg((const float4*)(hin + (size_t)(bN + j0) * HH) + lane);
        float4 v1 = __ldg((const float4*)(hin + (size_t)(bN + j1) * HH) + lane);
        float4 v2 = __ldg((const float4*)(hin + (size_t)(bN + j2) * HH) + lane);
        float4 v3 = __ldg((const float4*)(hin + (size_t)(bN + j3) * HH) + lane);
        a.x = __fadd_rn(a.x, v0.x); a.y = __fadd_rn(a.y, v0.y);
        a.z = __fadd_rn(a.z, v0.z); a.w = __fadd_rn(a.w, v0.w);
        a.x = __fadd_rn(a.x, v1.x); a.y = __fadd_rn(a.y, v1.y);
        a.z = __fadd_rn(a.z, v1.z); a.w = __fadd_rn(a.w, v1.w);
        a.x = __fadd_rn(a.x, v2.x); a.y = __fadd_rn(a.y, v2.y);
        a.z = __fadd_rn(a.z, v2.z); a.w = __fadd_rn(a.w, v2.w);
        a.x = __fadd_rn(a.x, v3.x); a.y = __fadd_rn(a.y, v3.y);
        a.z = __fadd_rn(a.z, v3.z); a.w = __fadd_rn(a.w, v3.w);
    }
    for (; t < cnt; t++) {
        float4 v = __ldg((const float4*)(hin + (size_t)(bN + nb[t]) * HH) + lane);
        a.x = __fadd_rn(a.x, v.x); a.y = __fadd_rn(a.y, v.y);
        a.z = __fadd_rn(a.z, v.z); a.w = __fadd_rn(a.w, v.w);
    }
    return a;
}

// ---------------- fused aggregate + dense GEMM, warp-local ------------------
// Warp w owns rows 8w..8w+7: gathers them, __syncwarp, then GEMMs them.
// No block-level A|B barrier -> gather latency overlaps FMA across warps.
// src==0: g_ha -> g_hb ; src==1: g_hb -> g_ha.
// grid (BD*NN/64), 256 threads, dynamic smem (~98KB, 2 CTAs/SM).
__global__ __launch_bounds__(256, 2) void k_aggemm(int src,
                                                   const float* __restrict__ bias,
                                                   const float* __restrict__ W) {
    extern __shared__ __align__(16) float sm[];
    float* Ws = sm;                 // 128*128
    float* xs = sm + HH * HH;       // 64*132 (float4-aligned pitch)
    float* dj = xs + 64 * 132;      // 64
    float* bs = dj + 64;            // 128

    const float* hin  = src ? g_hb : g_ha;
    float*       hout = src ? g_ha : g_hb;

    int row0 = blockIdx.x * 64;
    int tid = threadIdx.x;
    int bN = (row0 / NN) * NN;       // neighbors are batch-local ids

    for (int k = tid; k < HH * HH; k += 256) Ws[k] = W[k];
    if (tid < HH) bs[tid] = bias[tid];
    if (tid < 64) dj[tid] = g_dinv[row0 + tid];
    __syncthreads();                 // only sync: W/bias/dinv visible

    int warp = tid >> 5, lane = tid & 31;
    int rbase = warp * 8;

    // Phase A (warp-local): gather own 8 rows into xs
    #pragma unroll 1
    for (int rr = 0; rr < 8; rr++) {
        int r = rbase + rr;
        int i = row0 + r;
        float4 a = gather_row(hin, g_nbr + (size_t)i * MAXN, g_cnt[i], bN, lane);
        float di = dj[r];
        float4 bb = ((const float4*)bs)[lane];
        float4 o;
        o.x = fmaxf(__fadd_rn(__fmul_rn(a.x, di), bb.x), 0.f);
        o.y = fmaxf(__fadd_rn(__fmul_rn(a.y, di), bb.y), 0.f);
        o.z = fmaxf(__fadd_rn(__fmul_rn(a.z, di), bb.z), 0.f);
        o.w = fmaxf(__fadd_rn(__fmul_rn(a.w, di), bb.w), 0.f);
        *(float4*)&xs[r * 132 + lane * 4] = o;
    }
    __syncwarp();                    // order xs writes vs reads within warp

    // Phase B (warp-local): rows rbase..rbase+7, cols lane*4..lane*4+3.
    // k strictly ascending per (row,col) accumulator — bit-identical chain.
    float acc[8][4];
    #pragma unroll
    for (int rr = 0; rr < 8; rr++)
        #pragma unroll
        for (int c = 0; c < 4; c++) acc[rr][c] = 0.f;

    #pragma unroll 2
    for (int k0 = 0; k0 < HH; k0 += 4) {
        float4 xv[8];
        #pragma unroll
        for (int rr = 0; rr < 8; rr++)
            xv[rr] = *(const float4*)&xs[(rbase + rr) * 132 + k0];
        #pragma unroll
        for (int kk = 0; kk < 4; kk++) {
            float4 wk = *(const float4*)&Ws[(k0 + kk) * HH + lane * 4];
            #pragma unroll
            for (int rr = 0; rr < 8; rr++) {
                float xv_k = (kk == 0) ? xv[rr].x : (kk == 1) ? xv[rr].y
                           : (kk == 2) ? xv[rr].z : xv[rr].w;
                acc[rr][0] = fmaf(xv_k, wk.x, acc[rr][0]);
                acc[rr][1] = fmaf(xv_k, wk.y, acc[rr][1]);
                acc[rr][2] = fmaf(xv_k, wk.z, acc[rr][2]);
                acc[rr][3] = fmaf(xv_k, wk.w, acc[rr][3]);
            }
        }
    }

    #pragma unroll
    for (int rr = 0; rr < 8; rr++) {
        int r = rbase + rr;
        float d = dj[r];
        float4 o;
        o.x = __fmul_rn(acc[rr][0], d);
        o.y = __fmul_rn(acc[rr][1], d);
        o.z = __fmul_rn(acc[rr][2], d);
        o.w = __fmul_rn(acc[rr][3], d);
        *(float4*)&hout[(size_t)(row0 + r) * HH + lane * 4] = o;
    }
}

// ---------------- fused aggregate + fc head + state update, warp-local -----
// Reads g_ha (layer2 gemm output lands there).
__global__ __launch_bounds__(256) void k_aggfc(const float* __restrict__ bias2,
                                               const float* __restrict__ Wfc,
                                               const float* __restrict__ bfc,
                                               const float* __restrict__ padding,
                                               float* __restrict__ out, int t) {
    __shared__ __align__(16) float xs[64 * 132];
    __shared__ float Wf[HH * 6];
    __shared__ float bf[6];
    __shared__ __align__(16) float bs[HH];
    int row0 = blockIdx.x * 64;
    int tid = threadIdx.x;
    int bN = (row0 / NN) * NN;

    for (int k = tid; k < HH * 6; k += 256) Wf[k] = Wfc[k];
    if (tid < 6) bf[tid] = bfc[tid];
    if (tid < HH) bs[tid] = bias2[tid];
    __syncthreads();

    int warp = tid >> 5, lane = tid & 31;
    int rbase = warp * 8;
    #pragma unroll 1
    for (int rr = 0; rr < 8; rr++) {
        int r = rbase + rr;
        int i = row0 + r;
        float4 a = gather_row(g_ha, g_nbr + (size_t)i * MAXN, g_cnt[i], bN, lane);
        float di = g_dinv[i];
        float4 bb = ((const float4*)bs)[lane];
        float4 o;
        o.x = fmaxf(__fadd_rn(__fmul_rn(a.x, di), bb.x), 0.f);
        o.y = fmaxf(__fadd_rn(__fmul_rn(a.y, di), bb.y), 0.f);
        o.z = fmaxf(__fadd_rn(__fmul_rn(a.z, di), bb.z), 0.f);
        o.w = fmaxf(__fadd_rn(__fmul_rn(a.w, di), bb.w), 0.f);
        *(float4*)&xs[r * 132 + lane * 4] = o;
    }
    __syncwarp();

    // fc for own 8 rows: 48 outputs per warp, lanes strided.
    for (int w = lane; w < 8 * 6; w += 32) {
        int rr = w / 6, c = w % 6;
        int g = row0 + rbase + rr;
        const float* xr = xs + (rbase + rr) * 132;
        float acc = 0.f;
        #pragma unroll 8
        for (int k = 0; k < HH; k++) acc = fmaf(xr[k], Wf[k * 6 + c], acc);
        float res = __fadd_rn(acc, bf[c]);
        res = __fmul_rn(res, padding[g]);
        if (c < 3) {
            float p = __fadd_rn(g_pos[g * 3 + c], res);
            g_pos[g * 3 + c] = p;
            int b = g / NN, n = g % NN;
            out[((size_t)(b * (TT + 1) + t + 1) * NN + n) * 3 + c] = p;
        } else {
            int a = g * 3 + (c - 3);
            g_vel[a] = __fadd_rn(g_vel[a], res);
        }
    }
}

// ---------------- launch ----------------
extern "C" void kernel_launch(void* const* d_in, const int* in_sizes, int n_in,
                              void* d_out, int out_size) {
    const float* points  = (const float*)d_in[0];
    const float* padding = (const float*)d_in[5];
    const float* W0  = (const float*)d_in[6];
    const float* b0  = (const float*)d_in[7];
    const float* W1  = (const float*)d_in[8];
    const float* b1  = (const float*)d_in[9];
    const float* W2  = (const float*)d_in[10];
    const float* b2  = (const float*)d_in[11];
    const float* Wfc = (const float*)d_in[12];
    const float* bfc = (const float*)d_in[13];
    float* out = (float*)d_out;

    const int smem_ag = (HH * HH + 64 * 132 + 64 + HH) * (int)sizeof(float);
    cudaFuncSetAttribute(k_aggemm, cudaFuncAttributeMaxDynamicSharedMemorySize,
                         smem_ag);

    const int ROWS = BD * NN;

    k_init<<<(BD * NN * 3 + 255) / 256, 256>>>(points, out);

    for (int t = 0; t < TT; t++) {
        k_adj<<<dim3(NN / 64, BD), 256>>>(padding, W0);      // -> g_ha (h0)
        k_aggemm<<<ROWS / 64, 256, smem_ag>>>(0, b0, W1);    // ha -> x -> hb
        k_aggemm<<<ROWS / 64, 256, smem_ag>>>(1, b1, W2);    // hb -> x -> ha
        k_aggfc <<<ROWS / 64, 256>>>(b2, Wfc, bfc, padding, out, t);
    }
}